// round 12
// baseline (speedup 1.0000x reference)
#include <cuda_runtime.h>
#include <math.h>

#define N_USERS      100000
#define N_ITEMS      50000
#define N_ENTITIES   180000
#define N_USER_NODES 150000
#define N_REL        32
#define D            64
#define DV4          16   // D/4 float4 chunks per row

// ---------------- scratch (device globals; no allocation allowed) ----------
__device__ float g_eagg[(size_t)N_ENTITIES * D];      // entity_agg sums
__device__ float g_aagg[(size_t)N_USER_NODES * D];    // attribute_agg sums
__device__ float g_iu  [(size_t)N_ITEMS * D];         // i_u_agg sums
__device__ float g_ui  [(size_t)N_USERS * D];         // u_i_agg sums
__device__ float g_cnt_e [N_ENTITIES];
__device__ float g_cnt_a [N_USER_NODES];
__device__ float g_cnt_iu[N_ITEMS];
__device__ float g_cnt_ui[N_USERS];

__device__ __forceinline__ float4 mul4(float4 a, float4 b) {
    return make_float4(a.x * b.x, a.y * b.y, a.z * b.z, a.w * b.w);
}

// ---------------- zero scratch each launch ---------------------------------
__global__ void zero_all() {
    int gid = blockIdx.x * blockDim.x + threadIdx.x;
    int stride = gridDim.x * blockDim.x;
    float4 z = make_float4(0.f, 0.f, 0.f, 0.f);
#define ZLOOP(arr, n4) { float4* p = (float4*)(arr); \
    for (int i = gid; i < (n4); i += stride) p[i] = z; }
    ZLOOP(g_eagg, N_ENTITIES * DV4)
    ZLOOP(g_aagg, N_USER_NODES * DV4)
    ZLOOP(g_iu,   N_ITEMS * DV4)
    ZLOOP(g_ui,   N_USERS * DV4)
    ZLOOP(g_cnt_e,  N_ENTITIES / 4)
    ZLOOP(g_cnt_a,  N_USER_NODES / 4)
    ZLOOP(g_cnt_iu, N_ITEMS / 4)
    ZLOOP(g_cnt_ui, N_USERS / 4)
#undef ZLOOP
}

// ---------------- typed scatter body (index-prefetch pipeline) -------------
__device__ __forceinline__ void scatter_body_pf(
    const float4* __restrict__ emb, const float4* __restrict__ sw,
    const int* __restrict__ head, const int* __restrict__ tail,
    const int* __restrict__ etype,
    float4* __restrict__ agg, float* __restrict__ cnt, int n_edges,
    int blk, int nblocks)
{
    int gid = blk * 256 + threadIdx.x;
    int c = gid & 15;
    int stride = nblocks * 256;
    int total = n_edges << 4;

    int g = gid;
    if (g >= total) return;
    int e = g >> 4;
    int h  = __ldg(head + e);
    int t  = __ldg(tail + e);
    int ty = __ldg(etype + e);

    while (true) {
        int gn = g + stride;
        bool more = gn < total;
        int hn = 0, tn = 0, tyn = 0;
        if (more) {
            int en = gn >> 4;
            hn  = __ldg(head + en);
            tn  = __ldg(tail + en);
            tyn = __ldg(etype + en);
        }
        float4 v = __ldg(emb + t * DV4 + c);
        float4 w = sw[ty * DV4 + c];
        atomicAdd(agg + h * DV4 + c, mul4(v, w));
        if (c == 0) atomicAdd(cnt + h, 1.0f);
        if (!more) break;
        g = gn; h = hn; t = tn; ty = tyn;
    }
}

__device__ __forceinline__ void scatter_mat_body(
    const float4* __restrict__ uemb, const float4* __restrict__ eemb,
    float4 w0, const int* __restrict__ mrow, const int* __restrict__ mcol,
    int n, int blk, int nblocks)
{
    int gid = blk * 256 + threadIdx.x;
    int c = gid & 15;
    int stride = nblocks * 256;
    float4* iu = (float4*)g_iu;
    float4* ui = (float4*)g_ui;
    int total = n << 4;

    int g = gid;
    if (g >= total) return;
    int e = g >> 4;
    int r  = __ldg(mrow + e);
    int cl = __ldg(mcol + e);

    while (true) {
        int gn = g + stride;
        bool more = gn < total;
        int rn = 0, cln = 0;
        if (more) {
            int en = gn >> 4;
            rn  = __ldg(mrow + en);
            cln = __ldg(mcol + en);
        }
        float4 uv = __ldg(uemb + r  * DV4 + c);
        float4 ev = __ldg(eemb + cl * DV4 + c);
        atomicAdd(iu + cl * DV4 + c, mul4(uv, w0));
        atomicAdd(ui + r  * DV4 + c, mul4(ev, w0));
        if (c == 0) {
            atomicAdd(g_cnt_iu + cl, 1.0f);
            atomicAdd(g_cnt_ui + r,  1.0f);
        }
        if (!more) break;
        g = gn; r = rn; cl = cln;
    }
}

// ---------------- fused scatter: all three workloads in one wave -----------
__global__ void __launch_bounds__(256, 8)
scatter_all(const float4* __restrict__ eemb, const float4* __restrict__ uemb,
            const float4* __restrict__ weight,
            const int* __restrict__ e_head, const int* __restrict__ e_tail,
            const int* __restrict__ e_type, int n_e,
            const int* __restrict__ u_head, const int* __restrict__ u_tail,
            const int* __restrict__ u_type, int n_ue,
            const int* __restrict__ mrow, const int* __restrict__ mcol, int n_m,
            int b_e, int b_u)
{
    __shared__ float4 sw[N_REL * DV4];
    int b = blockIdx.x;
    if (b < b_u) {
        for (int i = threadIdx.x; i < N_REL * DV4; i += blockDim.x)
            sw[i] = __ldg(weight + i);
    }
    __syncthreads();

    if (b < b_e) {
        scatter_body_pf(eemb, sw, e_head, e_tail, e_type,
                        (float4*)g_eagg, g_cnt_e, n_e, b, b_e);
    } else if (b < b_u) {
        scatter_body_pf(uemb, sw, u_head, u_tail, u_type,
                        (float4*)g_aagg, g_cnt_a, n_ue, b - b_e, b_u - b_e);
    } else {
        float4 w0 = __ldg(weight + (threadIdx.x & 15));
        scatter_mat_body(uemb, eemb, w0, mrow, mcol, n_m,
                         b - b_u, gridDim.x - b_u);
    }
}

// ---------------- gated fusion, K-split two-stage ----------------------------
// Z = A@GA^T + B@GB^T done as two K=64 stages sharing one operand buffer.
// Stage A stashes each thread's 16 blend a-values in registers before the
// buffer is overwritten by B. Smem: 64*GPAD*2 + 128 floats = ~34.5KB ->
// 5+ blocks/SM instead of 3.
#define GPAD 68
#define GATE_SMEM ((2 * 64 * GPAD + 128) * 4)

__device__ __forceinline__ void gate_body(
    const float* __restrict__ aggA, const float* __restrict__ cntA,
    const float* __restrict__ aggB, const float* __restrict__ cntB,
    const float* __restrict__ GA,   const float* __restrict__ GB,
    float* __restrict__ out, int nrows, int blk, int mode)
{
    extern __shared__ float sm[];
    float* As   = sm;               // [64][GPAD] current-stage operand^T
    float* Gs   = sm + 64 * GPAD;   // [64][GPAD] current-stage gate^T
    float* invA = Gs + 64 * GPAD;   // [64]
    float* invB = invA + 64;        // [64]

    int tid = threadIdx.x;
    int row0 = blk * 64;

    if (tid < 64) {
        int r = row0 + tid;
        invA[tid] = (r < nrows) ? 1.f / fmaxf(__ldg(cntA + r), 1.f) : 0.f;
    } else if (tid < 128) {
        int r = row0 + tid - 64;
        invB[tid - 64] = (r < nrows) ? 1.f / fmaxf(__ldg(cntB + r), 1.f) : 0.f;
    }
    __syncthreads();

    int tx = tid & 15, ty = tid >> 4;
    const float4* As4 = (const float4*)As;
    const float4* Gs4 = (const float4*)Gs;
    float acc[4][4] = {};
    float ast[4][4];

    // ---- stage A: operand = aggA/invA, gate = GA ----
    for (int idx = tid; idx < 64 * 64; idx += 256) {
        int r = idx >> 6, k = idx & 63;
        int row = row0 + r;
        As[k * GPAD + r] = (row < nrows) ? aggA[(size_t)row * D + k] * invA[r] : 0.f;
    }
    for (int idx = tid; idx < 64 * 64; idx += 256) {
        int j = idx >> 6, k = idx & 63;
        Gs[k * GPAD + j] = __ldg(GA + idx);
    }
    __syncthreads();

#pragma unroll
    for (int j = 0; j < 4; j++) {       // stash a-values (vectorized along r)
        float4 v = As4[(tx * 4 + j) * (GPAD / 4) + ty];
        ast[0][j] = v.x; ast[1][j] = v.y; ast[2][j] = v.z; ast[3][j] = v.w;
    }
#pragma unroll 4
    for (int k = 0; k < 64; k++) {
        float4 av = As4[k * (GPAD / 4) + ty];
        float4 gv = Gs4[k * (GPAD / 4) + tx];
        float a_[4] = {av.x, av.y, av.z, av.w};
        float g_[4] = {gv.x, gv.y, gv.z, gv.w};
#pragma unroll
        for (int i = 0; i < 4; i++)
#pragma unroll
            for (int j = 0; j < 4; j++)
                acc[i][j] += a_[i] * g_[j];
    }
    __syncthreads();

    // ---- stage B: operand = aggB/invB, gate = GB ----
    for (int idx = tid; idx < 64 * 64; idx += 256) {
        int r = idx >> 6, k = idx & 63;
        int row = row0 + r;
        As[k * GPAD + r] = (row < nrows) ? aggB[(size_t)row * D + k] * invB[r] : 0.f;
    }
    for (int idx = tid; idx < 64 * 64; idx += 256) {
        int j = idx >> 6, k = idx & 63;
        Gs[k * GPAD + j] = __ldg(GB + idx);
    }
    __syncthreads();

#pragma unroll 4
    for (int k = 0; k < 64; k++) {
        float4 av = As4[k * (GPAD / 4) + ty];
        float4 gv = Gs4[k * (GPAD / 4) + tx];
        float a_[4] = {av.x, av.y, av.z, av.w};
        float g_[4] = {gv.x, gv.y, gv.z, gv.w};
#pragma unroll
        for (int i = 0; i < 4; i++)
#pragma unroll
            for (int j = 0; j < 4; j++)
                acc[i][j] += a_[i] * g_[j];
    }

    // ---- blend + store (b still resident in As) ----
    float bst[4][4];
#pragma unroll
    for (int j = 0; j < 4; j++) {
        float4 v = As4[(tx * 4 + j) * (GPAD / 4) + ty];
        bst[0][j] = v.x; bst[1][j] = v.y; bst[2][j] = v.z; bst[3][j] = v.w;
    }
#pragma unroll
    for (int i = 0; i < 4; i++) {
        int r = ty * 4 + i;
        int row = row0 + r;
        if (row >= nrows) continue;
        float4 o;
        float* op = &o.x;
#pragma unroll
        for (int j = 0; j < 4; j++) {
            float gate = 1.f / (1.f + __expf(-acc[i][j]));
            float a = ast[i][j], b = bst[i][j];
            op[j] = mode ? (gate * b + (1.f - gate) * a)
                         : (gate * a + (1.f - gate) * b);
        }
        *(float4*)(out + (size_t)row * D + tx * 4) = o;
    }
}

// ---------------- fused epilogue: gate0 | gate1 | normalize tails ----------
__global__ void __launch_bounds__(256, 5)
epilogue(const float* __restrict__ g1, const float* __restrict__ g2,
         const float* __restrict__ g3,
         float* __restrict__ out, float* __restrict__ user_out,
         int nb0, int nb1)
{
    int b = blockIdx.x;
    if (b < nb0) {
        gate_body(g_eagg, g_cnt_e, g_iu, g_cnt_iu, g1, g2, out, N_ITEMS, b, 0);
    } else if (b < nb0 + nb1) {
        gate_body(g_ui, g_cnt_ui, g_aagg, g_cnt_a, g2, g3, user_out, N_USERS,
                  b - nb0, 1);
    } else {
        // normalize tails: entity rows [N_ITEMS,N_ENTITIES), user rows [N_USERS,N_USER_NODES)
        int nb = gridDim.x - nb0 - nb1;
        int gid = (b - nb0 - nb1) * 256 + threadIdx.x;
        int stride = nb * 256;
        const int nE = (N_ENTITIES - N_ITEMS) * DV4;        // 2,080,000
        const int nU = (N_USER_NODES - N_USERS) * DV4;      //   800,000
        for (int i = gid; i < nE + nU; i += stride) {
            const float* agg; const float* cnt; float* dst; int r; int c;
            if (i < nE) {
                r = N_ITEMS + (i >> 4); c = i & 15;
                agg = g_eagg; cnt = g_cnt_e; dst = out;
            } else {
                int k = i - nE;
                r = N_USERS + (k >> 4); c = k & 15;
                agg = g_aagg; cnt = g_cnt_a; dst = user_out;
            }
            float ic = 1.f / fmaxf(__ldg(cnt + r), 1.f);
            float4 v = ((const float4*)agg)[(size_t)r * DV4 + c];
            ((float4*)dst)[(size_t)r * DV4 + c] =
                make_float4(v.x * ic, v.y * ic, v.z * ic, v.w * ic);
        }
    }
}

// ---------------- launch -----------------------------------------------------
extern "C" void kernel_launch(void* const* d_in, const int* in_sizes, int n_in,
                              void* d_out, int out_size)
{
    const float* entity_emb = (const float*)d_in[0];
    const float* user_emb   = (const float*)d_in[1];
    const float* weight     = (const float*)d_in[2];
    const float* gate1_w    = (const float*)d_in[3];
    const float* gate2_w    = (const float*)d_in[4];
    const float* gate3_w    = (const float*)d_in[5];
    const int*   edge_index = (const int*)d_in[6];
    const int*   edge_type  = (const int*)d_in[7];
    const int*   uedge_index= (const int*)d_in[8];
    const int*   uedge_type = (const int*)d_in[9];
    const int*   mat_row    = (const int*)d_in[10];
    const int*   mat_col    = (const int*)d_in[11];

    int n_e  = in_sizes[7];    // 1,500,000
    int n_ue = in_sizes[9];    // 1,000,000
    int n_m  = in_sizes[10];   // 1,500,000

    float* out = (float*)d_out;
    float* user_out = out + (size_t)N_ENTITIES * D;

    cudaFuncSetAttribute(epilogue, cudaFuncAttributeMaxDynamicSharedMemorySize, GATE_SMEM);

    zero_all<<<2048, 256>>>();

    // Partition scatter blocks by L2-traffic share
    const int SG = 4736;
    double t_e = (double)n_e * 524.0;
    double t_u = (double)n_ue * 524.0;
    double t_m = (double)n_m * 1032.0;
    double tot = t_e + t_u + t_m;
    int b_e = (int)(SG * (t_e / tot) + 0.5);
    int b_u = b_e + (int)(SG * (t_u / tot) + 0.5);
    if (b_e < 1) b_e = 1;
    if (b_u <= b_e) b_u = b_e + 1;
    if (b_u >= SG) b_u = SG - 1;

    scatter_all<<<SG, 256>>>((const float4*)entity_emb, (const float4*)user_emb,
                             (const float4*)weight,
                             edge_index, edge_index + n_e, edge_type, n_e,
                             uedge_index, uedge_index + n_ue, uedge_type, n_ue,
                             mat_row, mat_col, n_m,
                             b_e, b_u);

    int nb0 = (N_ITEMS + 63) / 64;   // 782
    int nb1 = (N_USERS + 63) / 64;   // 1563
    int nbn = 1024;                  // normalize partition (grid-stride)
    epilogue<<<nb0 + nb1 + nbn, 256, GATE_SMEM>>>(gate1_w, gate2_w, gate3_w,
                                                  out, user_out, nb0, nb1);
}

// round 13
// speedup vs baseline: 1.0100x; 1.0100x over previous
#include <cuda_runtime.h>
#include <cuda_fp16.h>
#include <math.h>

#define N_USERS      100000
#define N_ITEMS      50000
#define N_ENTITIES   180000
#define N_USER_NODES 150000
#define N_REL        32
#define D            64
#define DV4          16   // D/4 float4 chunks per row

// ---------------- scratch (device globals; no allocation allowed) ----------
__device__ float g_eagg[(size_t)N_ENTITIES * D];      // entity_agg sums
__device__ float g_aagg[(size_t)N_USER_NODES * D];    // attribute_agg sums
__device__ float g_iu  [(size_t)N_ITEMS * D];         // i_u_agg sums
__device__ float g_ui  [(size_t)N_USERS * D];         // u_i_agg sums
__device__ float g_cnt_e [N_ENTITIES];
__device__ float g_cnt_a [N_USER_NODES];
__device__ float g_cnt_iu[N_ITEMS];
__device__ float g_cnt_ui[N_USERS];

// fp16 copies of the embedding tables (gather-bandwidth halving; 42MB total
// -> L2 resident). One uint2 = 4 halves = one 4-float chunk.
__device__ uint2 g_eemb_h[(size_t)N_ENTITIES * DV4];
__device__ uint2 g_uemb_h[(size_t)N_USER_NODES * DV4];

__device__ __forceinline__ float4 mul4(float4 a, float4 b) {
    return make_float4(a.x * b.x, a.y * b.y, a.z * b.z, a.w * b.w);
}

__device__ __forceinline__ uint2 f4_to_h4(float4 v) {
    __half2 lo = __floats2half2_rn(v.x, v.y);
    __half2 hi = __floats2half2_rn(v.z, v.w);
    uint2 o;
    o.x = *reinterpret_cast<unsigned*>(&lo);
    o.y = *reinterpret_cast<unsigned*>(&hi);
    return o;
}

__device__ __forceinline__ float4 h4_to_f4(uint2 p) {
    __half2 lo = *reinterpret_cast<__half2*>(&p.x);
    __half2 hi = *reinterpret_cast<__half2*>(&p.y);
    float2 f0 = __half22float2(lo);
    float2 f1 = __half22float2(hi);
    return make_float4(f0.x, f0.y, f1.x, f1.y);
}

// ---------------- prep: zero accumulators + build fp16 tables --------------
// Block partition: [0, zb) zeroes (123MB writes), [zb, grid) converts
// (84MB reads + 42MB writes). Roughly traffic-balanced.
__global__ void prep(const float4* __restrict__ eemb,
                     const float4* __restrict__ uemb, int zb)
{
    int b = blockIdx.x;
    if (b < zb) {
        int gid = b * 256 + threadIdx.x;
        int stride = zb * 256;
        float4 z = make_float4(0.f, 0.f, 0.f, 0.f);
#define ZLOOP(arr, n4) { float4* p = (float4*)(arr); \
        for (int i = gid; i < (n4); i += stride) p[i] = z; }
        ZLOOP(g_eagg, N_ENTITIES * DV4)
        ZLOOP(g_aagg, N_USER_NODES * DV4)
        ZLOOP(g_iu,   N_ITEMS * DV4)
        ZLOOP(g_ui,   N_USERS * DV4)
        ZLOOP(g_cnt_e,  N_ENTITIES / 4)
        ZLOOP(g_cnt_a,  N_USER_NODES / 4)
        ZLOOP(g_cnt_iu, N_ITEMS / 4)
        ZLOOP(g_cnt_ui, N_USERS / 4)
#undef ZLOOP
    } else {
        int nb = gridDim.x - zb;
        int gid = (b - zb) * 256 + threadIdx.x;
        int stride = nb * 256;
        const int nE = N_ENTITIES * DV4;
        const int nU = N_USER_NODES * DV4;
        for (int i = gid; i < nE; i += stride)
            g_eemb_h[i] = f4_to_h4(__ldg(eemb + i));
        for (int i = gid; i < nU; i += stride)
            g_uemb_h[i] = f4_to_h4(__ldg(uemb + i));
    }
}

// ---------------- typed scatter body (index-prefetch, fp16 gathers) --------
__device__ __forceinline__ void scatter_body_pf(
    const uint2* __restrict__ embh, const float4* __restrict__ sw,
    const int* __restrict__ head, const int* __restrict__ tail,
    const int* __restrict__ etype,
    float4* __restrict__ agg, float* __restrict__ cnt, int n_edges,
    int blk, int nblocks)
{
    int gid = blk * 256 + threadIdx.x;
    int c = gid & 15;
    int stride = nblocks * 256;
    int total = n_edges << 4;

    int g = gid;
    if (g >= total) return;
    int e = g >> 4;
    int h  = __ldg(head + e);
    int t  = __ldg(tail + e);
    int ty = __ldg(etype + e);

    while (true) {
        int gn = g + stride;
        bool more = gn < total;
        int hn = 0, tn = 0, tyn = 0;
        if (more) {
            int en = gn >> 4;
            hn  = __ldg(head + en);
            tn  = __ldg(tail + en);
            tyn = __ldg(etype + en);
        }
        float4 v = h4_to_f4(__ldg(embh + t * DV4 + c));
        float4 w = sw[ty * DV4 + c];
        atomicAdd(agg + h * DV4 + c, mul4(v, w));
        if (c == 0) atomicAdd(cnt + h, 1.0f);
        if (!more) break;
        g = gn; h = hn; t = tn; ty = tyn;
    }
}

__device__ __forceinline__ void scatter_mat_body(
    float4 w0, const int* __restrict__ mrow, const int* __restrict__ mcol,
    int n, int blk, int nblocks)
{
    int gid = blk * 256 + threadIdx.x;
    int c = gid & 15;
    int stride = nblocks * 256;
    float4* iu = (float4*)g_iu;
    float4* ui = (float4*)g_ui;
    int total = n << 4;

    int g = gid;
    if (g >= total) return;
    int e = g >> 4;
    int r  = __ldg(mrow + e);
    int cl = __ldg(mcol + e);

    while (true) {
        int gn = g + stride;
        bool more = gn < total;
        int rn = 0, cln = 0;
        if (more) {
            int en = gn >> 4;
            rn  = __ldg(mrow + en);
            cln = __ldg(mcol + en);
        }
        float4 uv = h4_to_f4(__ldg(g_uemb_h + r  * DV4 + c));
        float4 ev = h4_to_f4(__ldg(g_eemb_h + cl * DV4 + c));
        atomicAdd(iu + cl * DV4 + c, mul4(uv, w0));
        atomicAdd(ui + r  * DV4 + c, mul4(ev, w0));
        if (c == 0) {
            atomicAdd(g_cnt_iu + cl, 1.0f);
            atomicAdd(g_cnt_ui + r,  1.0f);
        }
        if (!more) break;
        g = gn; r = rn; cl = cln;
    }
}

// ---------------- fused scatter: all three workloads in one wave -----------
__global__ void __launch_bounds__(256, 8)
scatter_all(const float4* __restrict__ weight,
            const int* __restrict__ e_head, const int* __restrict__ e_tail,
            const int* __restrict__ e_type, int n_e,
            const int* __restrict__ u_head, const int* __restrict__ u_tail,
            const int* __restrict__ u_type, int n_ue,
            const int* __restrict__ mrow, const int* __restrict__ mcol, int n_m,
            int b_e, int b_u)
{
    __shared__ float4 sw[N_REL * DV4];
    int b = blockIdx.x;
    if (b < b_u) {
        for (int i = threadIdx.x; i < N_REL * DV4; i += blockDim.x)
            sw[i] = __ldg(weight + i);
    }
    __syncthreads();

    if (b < b_e) {
        scatter_body_pf(g_eemb_h, sw, e_head, e_tail, e_type,
                        (float4*)g_eagg, g_cnt_e, n_e, b, b_e);
    } else if (b < b_u) {
        scatter_body_pf(g_uemb_h, sw, u_head, u_tail, u_type,
                        (float4*)g_aagg, g_cnt_a, n_ue, b - b_e, b_u - b_e);
    } else {
        float4 w0 = __ldg(weight + (threadIdx.x & 15));
        scatter_mat_body(w0, mrow, mcol, n_m, b - b_u, gridDim.x - b_u);
    }
}

// ---------------- gated fusion, K-split two-stage ----------------------------
#define GPAD 68
#define GATE_SMEM ((2 * 64 * GPAD + 128) * 4)

__device__ __forceinline__ void gate_body(
    const float* __restrict__ aggA, const float* __restrict__ cntA,
    const float* __restrict__ aggB, const float* __restrict__ cntB,
    const float* __restrict__ GA,   const float* __restrict__ GB,
    float* __restrict__ out, int nrows, int blk, int mode)
{
    extern __shared__ float sm[];
    float* As   = sm;               // [64][GPAD] current-stage operand^T
    float* Gs   = sm + 64 * GPAD;   // [64][GPAD] current-stage gate^T
    float* invA = Gs + 64 * GPAD;   // [64]
    float* invB = invA + 64;        // [64]

    int tid = threadIdx.x;
    int row0 = blk * 64;

    if (tid < 64) {
        int r = row0 + tid;
        invA[tid] = (r < nrows) ? 1.f / fmaxf(__ldg(cntA + r), 1.f) : 0.f;
    } else if (tid < 128) {
        int r = row0 + tid - 64;
        invB[tid - 64] = (r < nrows) ? 1.f / fmaxf(__ldg(cntB + r), 1.f) : 0.f;
    }
    __syncthreads();

    int tx = tid & 15, ty = tid >> 4;
    const float4* As4 = (const float4*)As;
    const float4* Gs4 = (const float4*)Gs;
    float acc[4][4] = {};
    float ast[4][4];

    // ---- stage A ----
    for (int idx = tid; idx < 64 * 64; idx += 256) {
        int r = idx >> 6, k = idx & 63;
        int row = row0 + r;
        As[k * GPAD + r] = (row < nrows) ? aggA[(size_t)row * D + k] * invA[r] : 0.f;
    }
    for (int idx = tid; idx < 64 * 64; idx += 256) {
        int j = idx >> 6, k = idx & 63;
        Gs[k * GPAD + j] = __ldg(GA + idx);
    }
    __syncthreads();

#pragma unroll
    for (int j = 0; j < 4; j++) {
        float4 v = As4[(tx * 4 + j) * (GPAD / 4) + ty];
        ast[0][j] = v.x; ast[1][j] = v.y; ast[2][j] = v.z; ast[3][j] = v.w;
    }
#pragma unroll 4
    for (int k = 0; k < 64; k++) {
        float4 av = As4[k * (GPAD / 4) + ty];
        float4 gv = Gs4[k * (GPAD / 4) + tx];
        float a_[4] = {av.x, av.y, av.z, av.w};
        float g_[4] = {gv.x, gv.y, gv.z, gv.w};
#pragma unroll
        for (int i = 0; i < 4; i++)
#pragma unroll
            for (int j = 0; j < 4; j++)
                acc[i][j] += a_[i] * g_[j];
    }
    __syncthreads();

    // ---- stage B ----
    for (int idx = tid; idx < 64 * 64; idx += 256) {
        int r = idx >> 6, k = idx & 63;
        int row = row0 + r;
        As[k * GPAD + r] = (row < nrows) ? aggB[(size_t)row * D + k] * invB[r] : 0.f;
    }
    for (int idx = tid; idx < 64 * 64; idx += 256) {
        int j = idx >> 6, k = idx & 63;
        Gs[k * GPAD + j] = __ldg(GB + idx);
    }
    __syncthreads();

#pragma unroll 4
    for (int k = 0; k < 64; k++) {
        float4 av = As4[k * (GPAD / 4) + ty];
        float4 gv = Gs4[k * (GPAD / 4) + tx];
        float a_[4] = {av.x, av.y, av.z, av.w};
        float g_[4] = {gv.x, gv.y, gv.z, gv.w};
#pragma unroll
        for (int i = 0; i < 4; i++)
#pragma unroll
            for (int j = 0; j < 4; j++)
                acc[i][j] += a_[i] * g_[j];
    }

    // ---- blend + store ----
    float bst[4][4];
#pragma unroll
    for (int j = 0; j < 4; j++) {
        float4 v = As4[(tx * 4 + j) * (GPAD / 4) + ty];
        bst[0][j] = v.x; bst[1][j] = v.y; bst[2][j] = v.z; bst[3][j] = v.w;
    }
#pragma unroll
    for (int i = 0; i < 4; i++) {
        int r = ty * 4 + i;
        int row = row0 + r;
        if (row >= nrows) continue;
        float4 o;
        float* op = &o.x;
#pragma unroll
        for (int j = 0; j < 4; j++) {
            float gate = 1.f / (1.f + __expf(-acc[i][j]));
            float a = ast[i][j], b = bst[i][j];
            op[j] = mode ? (gate * b + (1.f - gate) * a)
                         : (gate * a + (1.f - gate) * b);
        }
        *(float4*)(out + (size_t)row * D + tx * 4) = o;
    }
}

// ---------------- fused epilogue: gate0 | gate1 | normalize tails ----------
__global__ void __launch_bounds__(256, 5)
epilogue(const float* __restrict__ g1, const float* __restrict__ g2,
         const float* __restrict__ g3,
         float* __restrict__ out, float* __restrict__ user_out,
         int nb0, int nb1)
{
    int b = blockIdx.x;
    if (b < nb0) {
        gate_body(g_eagg, g_cnt_e, g_iu, g_cnt_iu, g1, g2, out, N_ITEMS, b, 0);
    } else if (b < nb0 + nb1) {
        gate_body(g_ui, g_cnt_ui, g_aagg, g_cnt_a, g2, g3, user_out, N_USERS,
                  b - nb0, 1);
    } else {
        int nb = gridDim.x - nb0 - nb1;
        int gid = (b - nb0 - nb1) * 256 + threadIdx.x;
        int stride = nb * 256;
        const int nE = (N_ENTITIES - N_ITEMS) * DV4;        // 2,080,000
        const int nU = (N_USER_NODES - N_USERS) * DV4;      //   800,000
        for (int i = gid; i < nE + nU; i += stride) {
            const float* agg; const float* cnt; float* dst; int r; int c;
            if (i < nE) {
                r = N_ITEMS + (i >> 4); c = i & 15;
                agg = g_eagg; cnt = g_cnt_e; dst = out;
            } else {
                int k = i - nE;
                r = N_USERS + (k >> 4); c = k & 15;
                agg = g_aagg; cnt = g_cnt_a; dst = user_out;
            }
            float ic = 1.f / fmaxf(__ldg(cnt + r), 1.f);
            float4 v = ((const float4*)agg)[(size_t)r * DV4 + c];
            ((float4*)dst)[(size_t)r * DV4 + c] =
                make_float4(v.x * ic, v.y * ic, v.z * ic, v.w * ic);
        }
    }
}

// ---------------- launch -----------------------------------------------------
extern "C" void kernel_launch(void* const* d_in, const int* in_sizes, int n_in,
                              void* d_out, int out_size)
{
    const float* entity_emb = (const float*)d_in[0];
    const float* user_emb   = (const float*)d_in[1];
    const float* weight     = (const float*)d_in[2];
    const float* gate1_w    = (const float*)d_in[3];
    const float* gate2_w    = (const float*)d_in[4];
    const float* gate3_w    = (const float*)d_in[5];
    const int*   edge_index = (const int*)d_in[6];
    const int*   edge_type  = (const int*)d_in[7];
    const int*   uedge_index= (const int*)d_in[8];
    const int*   uedge_type = (const int*)d_in[9];
    const int*   mat_row    = (const int*)d_in[10];
    const int*   mat_col    = (const int*)d_in[11];

    int n_e  = in_sizes[7];    // 1,500,000
    int n_ue = in_sizes[9];    // 1,000,000
    int n_m  = in_sizes[10];   // 1,500,000

    float* out = (float*)d_out;
    float* user_out = out + (size_t)N_ENTITIES * D;

    cudaFuncSetAttribute(epilogue, cudaFuncAttributeMaxDynamicSharedMemorySize, GATE_SMEM);

    // zero (123MB writes) + fp16 table build (126MB traffic), traffic-balanced
    prep<<<4096, 256>>>((const float4*)entity_emb, (const float4*)user_emb, 2008);

    // Partition scatter blocks by L2-traffic share (fp16 gathers):
    //   kg edge:  128B gather + 256B RED + 12B idx = 396B
    //   mat edge: 256B gather + 512B RED + 8B idx  = 776B
    const int SG = 4736;
    double t_e = (double)n_e * 396.0;
    double t_u = (double)n_ue * 396.0;
    double t_m = (double)n_m * 776.0;
    double tot = t_e + t_u + t_m;
    int b_e = (int)(SG * (t_e / tot) + 0.5);
    int b_u = b_e + (int)(SG * (t_u / tot) + 0.5);
    if (b_e < 1) b_e = 1;
    if (b_u <= b_e) b_u = b_e + 1;
    if (b_u >= SG) b_u = SG - 1;

    scatter_all<<<SG, 256>>>((const float4*)weight,
                             edge_index, edge_index + n_e, edge_type, n_e,
                             uedge_index, uedge_index + n_ue, uedge_type, n_ue,
                             mat_row, mat_col, n_m,
                             b_e, b_u);

    int nb0 = (N_ITEMS + 63) / 64;   // 782
    int nb1 = (N_USERS + 63) / 64;   // 1563
    int nbn = 1024;                  // normalize partition (grid-stride)
    epilogue<<<nb0 + nb1 + nbn, 256, GATE_SMEM>>>(gate1_w, gate2_w, gate3_w,
                                                  out, user_out, nb0, nb1);
}